// round 7
// baseline (speedup 1.0000x reference)
#include <cuda_runtime.h>
#include <cstdint>

#define NN 100000
#define NE 1600000
#define D 128
#define EDIM 16
#define TILE_M 32
#define SCAN_BLK 1024
#define NSCAN ((NN + SCAN_BLK - 1) / SCAN_BLK)   // 98

// ---------------------------------------------------------------------------
// Scratch lives inside d_out's eh region (out + NN*D, 25.6M floats = 102MB).
// Layout (float slots relative to E = out + NN*D):
//   agg  : [0, NN*D)                  12.8M floats
//   esrc : [NN*D, NN*D+NE)            1.6M ints
//   cnt/off/cur : NN ints each
//   bsum : NSCAN ints
//   dis  : NN floats
// Total ~14.8M slots < 25.6M. The eh copy kernel runs LAST and overwrites
// this region with the real eh passthrough data.
// ---------------------------------------------------------------------------
#define AGG_OFF   0
#define ESRC_OFF  ((size_t)NN * D)
#define CNT_OFF   (ESRC_OFF + NE)
#define OFF_OFF   (CNT_OFF + NN)
#define CUR_OFF   (OFF_OFF + NN)
#define BSUM_OFF  (CUR_OFF + NN)
#define DIS_OFF   (BSUM_OFF + NSCAN)

// ---------------------------------------------------------------------------
__global__ void zero_cnt_kernel(int* __restrict__ cnt) {
    int i = blockIdx.x * blockDim.x + threadIdx.x;
    if (i < NN) cnt[i] = 0;
}

// ---------------------------------------------------------------------------
// Count in-degree of each destination. edge_index is INT32 (JAX x64-disabled
// canonicalizes the reference's jnp.int64 request down to int32).
// ---------------------------------------------------------------------------
__global__ void count_kernel(const int* __restrict__ dst,
                             int* __restrict__ cnt) {
    int e = blockIdx.x * blockDim.x + threadIdx.x;
    if (e < NE) atomicAdd(&cnt[dst[e]], 1);
}

// ---------------------------------------------------------------------------
// Block-level exclusive scan of cnt -> off (partial), block totals -> bsum
// ---------------------------------------------------------------------------
__global__ __launch_bounds__(SCAN_BLK) void scan1_kernel(
    const int* __restrict__ cnt, int* __restrict__ off, int* __restrict__ bsum)
{
    __shared__ int s[SCAN_BLK];
    int gid = blockIdx.x * SCAN_BLK + threadIdx.x;
    int v = (gid < NN) ? cnt[gid] : 0;
    s[threadIdx.x] = v;
    __syncthreads();
    #pragma unroll
    for (int o = 1; o < SCAN_BLK; o <<= 1) {
        int t = (threadIdx.x >= o) ? s[threadIdx.x - o] : 0;
        __syncthreads();
        s[threadIdx.x] += t;
        __syncthreads();
    }
    if (gid < NN) off[gid] = s[threadIdx.x] - v;   // exclusive
    if (threadIdx.x == SCAN_BLK - 1) bsum[blockIdx.x] = s[SCAN_BLK - 1];
}

// ---------------------------------------------------------------------------
__global__ void scan2_kernel(int* __restrict__ bsum) {
    if (threadIdx.x == 0 && blockIdx.x == 0) {
        int acc = 0;
        for (int i = 0; i < NSCAN; i++) { int t = bsum[i]; bsum[i] = acc; acc += t; }
    }
}

// ---------------------------------------------------------------------------
// Finalize offsets, init bucket cursors, compute deg^{-1/2}
// ---------------------------------------------------------------------------
__global__ void finalize_kernel(const int* __restrict__ cnt,
                                const int* __restrict__ bsum,
                                int* __restrict__ off, int* __restrict__ cur,
                                float* __restrict__ dis)
{
    int i = blockIdx.x * blockDim.x + threadIdx.x;
    if (i < NN) {
        int o = off[i] + bsum[i >> 10];
        off[i] = o;
        cur[i] = o;
        int c = cnt[i];
        dis[i] = (c > 0) ? rsqrtf((float)c) : 0.f;
    }
}

// ---------------------------------------------------------------------------
// Bucket: place each edge's src into its destination's CSR segment
// ---------------------------------------------------------------------------
__global__ void bucket_kernel(const int* __restrict__ src,
                              const int* __restrict__ dst,
                              int* __restrict__ cur, int* __restrict__ esrc)
{
    int e = blockIdx.x * blockDim.x + threadIdx.x;
    if (e < NE) {
        int d = dst[e];
        int pos = atomicAdd(&cur[d], 1);
        esrc[pos] = src[e];
    }
}

// ---------------------------------------------------------------------------
// Aggregate: one warp per destination node, lane = one float4 of the row.
// agg[n] = dis[n] * sum_{e in CSR[n]} dis[src_e] * nh[src_e]
// nh (51MB) is L2-resident; each output row written exactly once (no float
// atomics anywhere in the pipeline).
// ---------------------------------------------------------------------------
__global__ __launch_bounds__(256) void aggregate_kernel(
    const float* __restrict__ nh, const int* __restrict__ esrc,
    const int* __restrict__ off, const int* __restrict__ cnt,
    const float* __restrict__ dis, float* __restrict__ agg)
{
    int n = (blockIdx.x * blockDim.x + threadIdx.x) >> 5;
    int lane = threadIdx.x & 31;
    if (n >= NN) return;
    int beg = off[n];
    int c = cnt[n];
    const float4* nh4 = (const float4*)nh;
    float4 acc = make_float4(0.f, 0.f, 0.f, 0.f);
    for (int i = 0; i < c; i++) {
        int s = esrc[beg + i];
        float sc = dis[s];
        float4 v = nh4[(size_t)s * (D / 4) + lane];
        acc.x += sc * v.x; acc.y += sc * v.y;
        acc.z += sc * v.z; acc.w += sc * v.w;
    }
    float dn = dis[n];
    acc.x *= dn; acc.y *= dn; acc.z *= dn; acc.w *= dn;
    ((float4*)agg)[(size_t)n * (D / 4) + lane] = acc;
}

// ---------------------------------------------------------------------------
// One MLP layer: out[m][j] = act( sum_i in[m][i] * W[i][j] + b[j] )
// 128 threads, one 32-node tile per block. A tile in static smem (stride 129,
// conflict-free). W (64KB) streamed from global -> L1-resident across block
// rereads. Register tiling 8 rows x 4 cols per thread -> FFMA-pipe bound.
// ---------------------------------------------------------------------------
__global__ __launch_bounds__(128) void mlp_kernel(
    const float* __restrict__ in, const float* __restrict__ W,
    const float* __restrict__ b, float* out, int apply_relu)
{
    __shared__ float As[TILE_M * 129];   // ~16.5KB

    int tid = threadIdx.x;
    int m0 = blockIdx.x * TILE_M;

    for (int idx = tid; idx < TILE_M * D; idx += 128) {
        int r = idx >> 7, c = idx & 127;
        As[r * 129 + c] = in[(size_t)(m0 + r) * D + c];
    }
    __syncthreads();

    int cg = tid & 31;   // column group: cols [4cg, 4cg+3]
    int rg = tid >> 5;   // warp id: rows [8rg, 8rg+7]
    float4 bias = ((const float4*)b)[cg];

    float acc[8][4];
    #pragma unroll
    for (int m = 0; m < 8; m++) {
        acc[m][0] = bias.x; acc[m][1] = bias.y;
        acc[m][2] = bias.z; acc[m][3] = bias.w;
    }

    const float* Arow = As + rg * 8 * 129;
    const float4* Wv = (const float4*)W;
    #pragma unroll 4
    for (int i = 0; i < D; i++) {
        float4 w = Wv[i * 32 + cg];
        #pragma unroll
        for (int m = 0; m < 8; m++) {
            float a = Arow[m * 129 + i];
            acc[m][0] += a * w.x;
            acc[m][1] += a * w.y;
            acc[m][2] += a * w.z;
            acc[m][3] += a * w.w;
        }
    }

    #pragma unroll
    for (int m = 0; m < 8; m++) {
        float4 r = make_float4(acc[m][0], acc[m][1], acc[m][2], acc[m][3]);
        if (apply_relu) {
            r.x = fmaxf(r.x, 0.f); r.y = fmaxf(r.y, 0.f);
            r.z = fmaxf(r.z, 0.f); r.w = fmaxf(r.w, 0.f);
        }
        ((float4*)(out + (size_t)(m0 + rg * 8 + m) * D))[cg] = r;
    }
}

// ---------------------------------------------------------------------------
// eh passthrough — runs LAST, overwriting the scratch region with real data
// ---------------------------------------------------------------------------
__global__ void copy_eh_kernel(const float4* __restrict__ src,
                               float4* __restrict__ dst, int n4) {
    int i = blockIdx.x * blockDim.x + threadIdx.x;
    int stride = gridDim.x * blockDim.x;
    for (; i < n4; i += stride) dst[i] = src[i];
}

// ---------------------------------------------------------------------------
extern "C" void kernel_launch(void* const* d_in, const int* in_sizes, int n_in,
                              void* d_out, int out_size) {
    const float* nh = (const float*)d_in[0];
    const float* eh = (const float*)d_in[1];
    const int*   ei = (const int*)d_in[2];   // INT32: JAX x64-disabled
    const float* W1 = (const float*)d_in[3];
    const float* b1 = (const float*)d_in[4];
    const float* W2 = (const float*)d_in[5];
    const float* b2 = (const float*)d_in[6];
    float* out = (float*)d_out;

    const int* src = ei;        // row 0
    const int* dst = ei + NE;   // row 1

    // Scratch pointers inside the eh region of d_out
    float* E    = out + (size_t)NN * D;
    float* agg  = E + AGG_OFF;
    int*   esrc = (int*)(E + ESRC_OFF);
    int*   cnt  = (int*)(E + CNT_OFF);
    int*   off  = (int*)(E + OFF_OFF);
    int*   cur  = (int*)(E + CUR_OFF);
    int*   bsum = (int*)(E + BSUM_OFF);
    float* dis  = E + DIS_OFF;

    zero_cnt_kernel<<<(NN + 255) / 256, 256>>>(cnt);
    count_kernel<<<(NE + 255) / 256, 256>>>(dst, cnt);
    scan1_kernel<<<NSCAN, SCAN_BLK>>>(cnt, off, bsum);
    scan2_kernel<<<1, 32>>>(bsum);
    finalize_kernel<<<(NN + 255) / 256, 256>>>(cnt, bsum, off, cur, dis);
    bucket_kernel<<<(NE + 255) / 256, 256>>>(src, dst, cur, esrc);
    aggregate_kernel<<<(NN * 32 + 255) / 256, 256>>>(nh, esrc, off, cnt, dis, agg);
    mlp_kernel<<<NN / TILE_M, 128>>>(agg, W1, b1, agg, 1);   // in-place hidden
    mlp_kernel<<<NN / TILE_M, 128>>>(agg, W2, b2, out, 0);   // final output
    copy_eh_kernel<<<2048, 256>>>((const float4*)eh, (float4*)E, NE * EDIM / 4);
}